// round 8
// baseline (speedup 1.0000x reference)
#include <cuda_runtime.h>

#define NBATCH 4
#define NTOK   4096
#define DDIM   16
#define NB     64                    /* bins */
#define XLO    (-6.0f)
#define BINW   0.1875f               /* 12/64, exact in fp32 */
#define INVW   (64.0f / 12.0f)
#define L2E    1.44269504088896f
#define GX     32                    /* blocks per batch */
#define NTHR   128                   /* hist kernel: one thread per value */
#define NTHR2  256                   /* main kernel: 2 threads per row */
#define RPB    (NTOK / GX)           /* 128 rows per block */

// Per-(batch,slot) partial moment histograms, written (not accumulated) by k1.
// Layout per slot: 128 float4 — [0..63] = (n,M1,M2,M3), [64..127] = (M4,M5,0,0).
__device__ float4 g_part[NBATCH][GX][2 * NB];

__device__ __forceinline__ float ex2f(float v) {
    float r;
    asm("ex2.approx.ftz.f32 %0, %1;" : "=f"(r) : "f"(v));
    return r;
}

// ---------------- kernel 1: per-block partial histograms (128 values each) ----------------
__global__ __launch_bounds__(NTHR, 1)
void hist_kernel(const float* __restrict__ x)
{
    __shared__ float h[6][NB];

    const int b   = blockIdx.y;
    const int blk = blockIdx.x;
    const int tid = threadIdx.x;

    #pragma unroll
    for (int i = tid; i < 6 * NB; i += NTHR)
        (&h[0][0])[i] = 0.f;
    __syncthreads();

    {
        const float v = x[b * NTOK + blk * RPB + tid];
        int k = __float2int_rz((v - XLO) * INVW);
        k = max(0, min(NB - 1, k));
        float bc = fmaf((float)k + 0.5f, BINW, XLO);
        float d  = v - bc;
        float d2 = d * d;
        float d3 = d2 * d;
        atomicAdd(&h[0][k], 1.0f);
        atomicAdd(&h[1][k], d);
        atomicAdd(&h[2][k], d2);
        atomicAdd(&h[3][k], d3);
        atomicAdd(&h[4][k], d2 * d2);
        atomicAdd(&h[5][k], d3 * d2);
    }
    __syncthreads();

    float4 v4;
    if (tid < NB)
        v4 = make_float4(h[0][tid], h[1][tid], h[2][tid], h[3][tid]);
    else
        v4 = make_float4(h[4][tid - NB], h[5][tid - NB], 0.f, 0.f);
    g_part[b][blk][tid] = v4;
}

// ---------------- kernel 2: sum partials + per-row softmax-weighted sums ----------------
// 256 threads: pair (col, half) — half 0/1 each covers 16 slots / 32 bins.
__global__ __launch_bounds__(NTHR2, 1)
void main_kernel(const float* __restrict__ x,
                 const float* __restrict__ wq,
                 const float* __restrict__ wk,
                 const float* __restrict__ wv,
                 const float* __restrict__ wo,
                 float* __restrict__ out)
{
    __shared__ float4 shp[2][2 * NB];    // per-half partial column sums
    __shared__ float4 sha[NB];           // (n, M1, M2, M3)
    __shared__ float4 shb[NB];           // (M4, M5, -, -)
    __shared__ float  sr0[NTHR2];        // phase-C partial s0
    __shared__ float  sr1[NTHR2];        // phase-C partial s1

    const int b    = blockIdx.y;
    const int blk  = blockIdx.x;
    const int tid  = threadIdx.x;
    const int col  = tid & 127;          // histogram column / row index
    const int half = tid >> 7;           // 0 or 1
    const float* xb = x + b * NTOK;

    // ---- tiny dot products (redundant per thread, L1 broadcast) ----
    float c = 0.f, g = 0.f;
    #pragma unroll
    for (int i = 0; i < DDIM; i++) {
        c = fmaf(wq[i], wk[i], c);
        g = fmaf(wv[i], wo[i], g);
    }
    c *= 0.25f;   // 1/sqrt(ATTN_DIM), TAU = 1

    // ---- sum this thread's float4 column across its 16 slots (L2 hits, MLP 4) ----
    {
        float4 a0 = make_float4(0.f, 0.f, 0.f, 0.f);
        float4 a1 = make_float4(0.f, 0.f, 0.f, 0.f);
        float4 a2 = make_float4(0.f, 0.f, 0.f, 0.f);
        float4 a3 = make_float4(0.f, 0.f, 0.f, 0.f);
        const int s0i = half * (GX / 2);
        #pragma unroll
        for (int s = 0; s < GX / 2; s += 4) {
            float4 p0 = g_part[b][s0i + s + 0][col];
            float4 p1 = g_part[b][s0i + s + 1][col];
            float4 p2 = g_part[b][s0i + s + 2][col];
            float4 p3 = g_part[b][s0i + s + 3][col];
            a0.x += p0.x; a0.y += p0.y; a0.z += p0.z; a0.w += p0.w;
            a1.x += p1.x; a1.y += p1.y; a1.z += p1.z; a1.w += p1.w;
            a2.x += p2.x; a2.y += p2.y; a2.z += p2.z; a2.w += p2.w;
            a3.x += p3.x; a3.y += p3.y; a3.z += p3.z; a3.w += p3.w;
        }
        shp[half][col] = make_float4(a0.x + a1.x + a2.x + a3.x,
                                     a0.y + a1.y + a2.y + a3.y,
                                     a0.z + a1.z + a2.z + a3.z,
                                     a0.w + a1.w + a2.w + a3.w);
    }
    __syncthreads();
    if (half == 0) {
        float4 u = shp[0][col], w = shp[1][col];
        float4 a = make_float4(u.x + w.x, u.y + w.y, u.z + w.z, u.w + w.w);
        if (col < NB) sha[col] = a;
        else          shb[col - NB] = a;
    }
    __syncthreads();

    // ---- phase C: each thread handles 32 bins of row 'col' ----
    {
        const float v = xb[blk * RPB + col];

        const float t  = c * v;
        const float u2 = 0.5f * t * t;
        const float u3 = u2 * t * (1.f / 3.f);
        const float u4 = u3 * t * 0.25f;
        const float u5 = u4 * t * 0.2f;
        const float A  = t * L2E;
        const float C0 = -fabsf(A) * 6.0f;       // global max-shift: arg <= 0

        const int   k0  = half * (NB / 2);
        float bb = fmaf((float)k0 + 0.5f, BINW, XLO);
        float e  = ex2f(fmaf(A, bb, C0));
        const float f = ex2f(A * BINW);

        float s0 = 0.f, s1 = 0.f;

        #pragma unroll
        for (int k = 0; k < NB / 2; k++) {
            float4 ma = sha[k0 + k];             // warp-uniform broadcast
            float4 mb = shb[k0 + k];
            float P = fmaf(t,  ma.y, ma.x);
            P       = fmaf(u2, ma.z, P);
            P       = fmaf(u3, ma.w, P);
            P       = fmaf(u4, mb.x, P);
            P       = fmaf(u5, mb.y, P);
            float Q = fmaf(t,  ma.z, ma.y);
            Q       = fmaf(u2, ma.w, Q);
            Q       = fmaf(u3, mb.x, Q);
            Q       = fmaf(u4, mb.y, Q);
            float r = fmaf(bb, P, Q);
            s0 = fmaf(e, P, s0);
            s1 = fmaf(e, r, s1);
            e *= f;
            bb += BINW;
        }

        sr0[tid] = s0;
        sr1[tid] = s1;
    }
    __syncthreads();

    if (half == 0) {
        float S0 = sr0[col] + sr0[col + 128];
        float S1 = sr1[col] + sr1[col + 128];
        out[b * NTOK + blk * RPB + col] = g * S1 / S0;
    }
}

extern "C" void kernel_launch(void* const* d_in, const int* in_sizes, int n_in,
                              void* d_out, int out_size)
{
    const float* x  = (const float*)d_in[0];
    const float* wq = (const float*)d_in[1];
    const float* wk = (const float*)d_in[2];
    const float* wv = (const float*)d_in[3];
    const float* wo = (const float*)d_in[4];
    float* out = (float*)d_out;

    hist_kernel<<<dim3(GX, NBATCH), NTHR>>>(x);
    main_kernel<<<dim3(GX, NBATCH), NTHR2>>>(x, wq, wk, wv, wo, out);
}

// round 9
// speedup vs baseline: 1.0029x; 1.0029x over previous
#include <cuda_runtime.h>

#define NBATCH 4
#define NTOK   4096
#define DDIM   16
#define NB     64                    /* bins */
#define XLO    (-6.0f)
#define BINW   0.1875f               /* 12/64, exact in fp32 */
#define INVW   (64.0f / 12.0f)
#define L2E    1.44269504088896f
#define GX     32                    /* blocks per batch */
#define NTHR   128                   /* hist kernel: one thread per value */
#define NTHR2  256                   /* main kernel: 2 threads per row */
#define RPB    (NTOK / GX)           /* 128 rows per block */

// Per-(batch,slot) partial moment histograms, written (not accumulated) by k1.
// Layout per slot: 128 float4 — [0..63] = (n,M1,M2,M3), [64..127] = (M4,M5,0,0).
__device__ float4 g_part[NBATCH][GX][2 * NB];

__device__ __forceinline__ float ex2f(float v) {
    float r;
    asm("ex2.approx.ftz.f32 %0, %1;" : "=f"(r) : "f"(v));
    return r;
}

// ---------------- kernel 1: per-block partial histograms (128 values each) ----------------
__global__ __launch_bounds__(NTHR, 1)
void hist_kernel(const float* __restrict__ x)
{
    __shared__ float h[6][NB];

    const int b   = blockIdx.y;
    const int blk = blockIdx.x;
    const int tid = threadIdx.x;

    // load early (DRAM/L2 latency overlaps the zero-fill)
    const float v = x[b * NTOK + blk * RPB + tid];

    #pragma unroll
    for (int i = tid; i < 6 * NB; i += NTHR)
        (&h[0][0])[i] = 0.f;
    __syncthreads();

    {
        int k = __float2int_rz((v - XLO) * INVW);
        k = max(0, min(NB - 1, k));
        float bc = fmaf((float)k + 0.5f, BINW, XLO);
        float d  = v - bc;
        float d2 = d * d;
        float d3 = d2 * d;
        atomicAdd(&h[0][k], 1.0f);
        atomicAdd(&h[1][k], d);
        atomicAdd(&h[2][k], d2);
        atomicAdd(&h[3][k], d3);
        atomicAdd(&h[4][k], d2 * d2);
        atomicAdd(&h[5][k], d3 * d2);
    }
    __syncthreads();

    float4 v4;
    if (tid < NB)
        v4 = make_float4(h[0][tid], h[1][tid], h[2][tid], h[3][tid]);
    else
        v4 = make_float4(h[4][tid - NB], h[5][tid - NB], 0.f, 0.f);
    g_part[b][blk][tid] = v4;

    // make stores visible, then release the dependent launch early
    __threadfence();
    cudaTriggerProgrammaticLaunchCompletion();
}

// ---------------- kernel 2: sum partials + per-row softmax-weighted sums ----------------
// Launched with PDL: everything before cudaGridDependencySynchronize() overlaps k1.
__global__ __launch_bounds__(NTHR2, 1)
void main_kernel(const float* __restrict__ x,
                 const float* __restrict__ wq,
                 const float* __restrict__ wk,
                 const float* __restrict__ wv,
                 const float* __restrict__ wo,
                 float* __restrict__ out)
{
    __shared__ float4 shp[2][2 * NB];    // per-half partial column sums
    __shared__ float4 sha[NB];           // (n, M1, M2, M3)
    __shared__ float4 shb[NB];           // (M4, M5, -, -)
    __shared__ float  sr0[NTHR2];        // phase-C partial s0
    __shared__ float  sr1[NTHR2];        // phase-C partial s1

    const int b    = blockIdx.y;
    const int blk  = blockIdx.x;
    const int tid  = threadIdx.x;
    const int col  = tid & 127;          // histogram column / row index
    const int half = tid >> 7;           // 0 or 1

    // ======== PRE-SYNC: everything independent of g_part ========

    // this thread's row value
    const float v = x[b * NTOK + blk * RPB + col];

    // tiny dot products (redundant per thread, L1 broadcast)
    float c = 0.f, g = 0.f;
    #pragma unroll
    for (int i = 0; i < DDIM; i++) {
        c = fmaf(wq[i], wk[i], c);
        g = fmaf(wv[i], wo[i], g);
    }
    c *= 0.25f;   // 1/sqrt(ATTN_DIM), TAU = 1

    // per-row exponent machinery (fully independent of the histogram)
    const float t  = c * v;
    const float u2 = 0.5f * t * t;
    const float u3 = u2 * t * (1.f / 3.f);
    const float u4 = u3 * t * 0.25f;
    const float u5 = u4 * t * 0.2f;
    const float A  = t * L2E;
    const float C0 = -fabsf(A) * 6.0f;           // global max-shift: arg <= 0
    const int   k0 = half * (NB / 2);
    float bb0 = fmaf((float)k0 + 0.5f, BINW, XLO);
    float e0v = ex2f(fmaf(A, bb0, C0));
    const float f = ex2f(A * BINW);

    // ======== wait for hist_kernel's g_part stores ========
    cudaGridDependencySynchronize();

    // ---- sum this thread's float4 column across its 16 slots (L2 hits) ----
    {
        float4 a0 = make_float4(0.f, 0.f, 0.f, 0.f);
        float4 a1 = make_float4(0.f, 0.f, 0.f, 0.f);
        float4 a2 = make_float4(0.f, 0.f, 0.f, 0.f);
        float4 a3 = make_float4(0.f, 0.f, 0.f, 0.f);
        const int s0i = half * (GX / 2);
        #pragma unroll
        for (int s = 0; s < GX / 2; s += 4) {
            float4 p0 = __ldcg(&g_part[b][s0i + s + 0][col]);
            float4 p1 = __ldcg(&g_part[b][s0i + s + 1][col]);
            float4 p2 = __ldcg(&g_part[b][s0i + s + 2][col]);
            float4 p3 = __ldcg(&g_part[b][s0i + s + 3][col]);
            a0.x += p0.x; a0.y += p0.y; a0.z += p0.z; a0.w += p0.w;
            a1.x += p1.x; a1.y += p1.y; a1.z += p1.z; a1.w += p1.w;
            a2.x += p2.x; a2.y += p2.y; a2.z += p2.z; a2.w += p2.w;
            a3.x += p3.x; a3.y += p3.y; a3.z += p3.z; a3.w += p3.w;
        }
        shp[half][col] = make_float4(a0.x + a1.x + a2.x + a3.x,
                                     a0.y + a1.y + a2.y + a3.y,
                                     a0.z + a1.z + a2.z + a3.z,
                                     a0.w + a1.w + a2.w + a3.w);
    }
    __syncthreads();
    if (half == 0) {
        float4 u = shp[0][col], w = shp[1][col];
        float4 a = make_float4(u.x + w.x, u.y + w.y, u.z + w.z, u.w + w.w);
        if (col < NB) sha[col] = a;
        else          shb[col - NB] = a;
    }
    __syncthreads();

    // ---- phase C: each thread handles 32 bins of row 'col' ----
    {
        float e  = e0v;
        float bb = bb0;
        float s0 = 0.f, s1 = 0.f;

        #pragma unroll
        for (int k = 0; k < NB / 2; k++) {
            float4 ma = sha[k0 + k];             // warp-uniform broadcast
            float4 mb = shb[k0 + k];
            float P = fmaf(t,  ma.y, ma.x);
            P       = fmaf(u2, ma.z, P);
            P       = fmaf(u3, ma.w, P);
            P       = fmaf(u4, mb.x, P);
            P       = fmaf(u5, mb.y, P);
            float Q = fmaf(t,  ma.z, ma.y);
            Q       = fmaf(u2, ma.w, Q);
            Q       = fmaf(u3, mb.x, Q);
            Q       = fmaf(u4, mb.y, Q);
            float r = fmaf(bb, P, Q);
            s0 = fmaf(e, P, s0);
            s1 = fmaf(e, r, s1);
            e *= f;
            bb += BINW;
        }

        sr0[tid] = s0;
        sr1[tid] = s1;
    }
    __syncthreads();

    if (half == 0) {
        float S0 = sr0[col] + sr0[col + 128];
        float S1 = sr1[col] + sr1[col + 128];
        out[b * NTOK + blk * RPB + col] = g * S1 / S0;
    }
}

extern "C" void kernel_launch(void* const* d_in, const int* in_sizes, int n_in,
                              void* d_out, int out_size)
{
    const float* x  = (const float*)d_in[0];
    const float* wq = (const float*)d_in[1];
    const float* wk = (const float*)d_in[2];
    const float* wv = (const float*)d_in[3];
    const float* wo = (const float*)d_in[4];
    float* out = (float*)d_out;

    hist_kernel<<<dim3(GX, NBATCH), NTHR>>>(x);

    // PDL launch: main may start while hist is still in flight; its
    // cudaGridDependencySynchronize() gates the g_part reads.
    cudaLaunchConfig_t cfg = {};
    cfg.gridDim  = dim3(GX, NBATCH);
    cfg.blockDim = dim3(NTHR2);
    cfg.dynamicSmemBytes = 0;
    cfg.stream = 0;
    cudaLaunchAttribute attrs[1];
    attrs[0].id = cudaLaunchAttributeProgrammaticStreamSerialization;
    attrs[0].val.programmaticStreamSerializationAllowed = 1;
    cfg.attrs = attrs;
    cfg.numAttrs = 1;
    cudaLaunchKernelEx(&cfg, main_kernel, x, wq, wk, wv, wo, out);
}